// round 1
// baseline (speedup 1.0000x reference)
#include <cuda_runtime.h>
#include <math.h>
#include <stdint.h>

// ---------------------------------------------------------------------------
// Problem constants
// ---------------------------------------------------------------------------
#define Bn    4096
#define DH    784
#define DE    16
#define NSR   5
#define NTOT  (Bn * (1 + NSR))    // 24576

__device__ __constant__ const float  A_C   = 1.576943f;
__device__ __constant__ const float  PW    = 1.7901216f;   // 2 * 0.8950608
__device__ __constant__ const float  EPSc  = 1e-4f;

// alpha/beta for BATCH_COUNT=500, TOTAL_STEPS=1000, WARMUP=50:
// beta = 0.5*(1 - 500/800)^2 = 0.0703125 ; alpha = 0.9296875
#define ALPHA 0.9296875
#define BETA  0.0703125

#define BM 128
#define BNt 128
#define BK 16

// ---------------------------------------------------------------------------
// Device scratch (no allocations allowed)
// ---------------------------------------------------------------------------
__device__ double g_Sh[Bn], g_Sl[Bn], g_Shh[Bn], g_Sll[Bn], g_Shl[Bn];
__device__ float  g_sqh[Bn];   // ||placeholder_i||^2
__device__ float  g_sql[Bn];   // ||e_to_i||^2
__device__ double g_ce;        // sum of CE terms

// ---------------------------------------------------------------------------
// Kernel 0: row norms + zero accumulators
// ---------------------------------------------------------------------------
__global__ void __launch_bounds__(128) prep_k(const float* __restrict__ X,
                                              const float* __restrict__ E) {
    int i = blockIdx.x;
    int t = threadIdx.x;
    const float* xr = X + (size_t)i * DH;
    float s = 0.f;
    for (int k = t; k < DH; k += 128) { float v = xr[k]; s = fmaf(v, v, s); }
    #pragma unroll
    for (int o = 16; o; o >>= 1) s += __shfl_xor_sync(0xffffffffu, s, o);
    __shared__ float ws[4];
    if ((t & 31) == 0) ws[t >> 5] = s;
    __syncthreads();
    if (t == 0) {
        g_sqh[i] = ws[0] + ws[1] + ws[2] + ws[3];
        const float* er = E + (size_t)i * 2 * DE;
        float sl = 0.f;
        #pragma unroll
        for (int k = 0; k < DE; k++) sl = fmaf(er[k], er[k], sl);
        g_sql[i] = sl;
        g_Sh[i] = 0.0; g_Sl[i] = 0.0; g_Shh[i] = 0.0; g_Sll[i] = 0.0; g_Shl[i] = 0.0;
        if (i == 0) g_ce = 0.0;
    }
}

// ---------------------------------------------------------------------------
// Kernel 1: fused pairwise-distance moment accumulation.
// Each block owns a 128x128 tile of the (i,j) plane. Computes the high-D gram
// via shared-memory SGEMM (K=784), converts gram -> distance, computes the
// low-D (16-dim) distance in the epilogue, accumulates 5 per-row moments.
// ---------------------------------------------------------------------------
__global__ void __launch_bounds__(256, 2) pair_k(const float* __restrict__ X,
                                                 const float* __restrict__ E) {
    __shared__ float As[BK][BM + 4];
    __shared__ float Bs[BK][BNt + 4];
    __shared__ float Ei[BM][20];   // e_to rows for i-tile (16 used, pad to 20)
    __shared__ float Ej[BNt][20];
    __shared__ float sqhI[BM], sqhJ[BNt], sqlI[BM], sqlJ[BNt];

    const int i0 = blockIdx.x * BM;
    const int j0 = blockIdx.y * BNt;
    const int tid = threadIdx.x;
    const int tx = tid & 15, ty = tid >> 4;

    // Load embedding tiles (first 16 of 32 floats per row = e_to) + norms.
    #pragma unroll
    for (int s = 0; s < 2; s++) {
        int id  = tid + s * 256;
        int row = id >> 2, q = id & 3;
        float4 vi = ((const float4*)E)[(size_t)(i0 + row) * 8 + q];
        *(float4*)&Ei[row][q * 4] = vi;
        float4 vj = ((const float4*)E)[(size_t)(j0 + row) * 8 + q];
        *(float4*)&Ej[row][q * 4] = vj;
    }
    if (tid < 128) {
        sqhI[tid] = g_sqh[i0 + tid];
        sqlI[tid] = g_sql[i0 + tid];
    } else {
        int r = tid - 128;
        sqhJ[r] = g_sqh[j0 + r];
        sqlJ[r] = g_sql[j0 + r];
    }

    float acc[8][8];
    #pragma unroll
    for (int a = 0; a < 8; a++)
        #pragma unroll
        for (int b = 0; b < 8; b++) acc[a][b] = 0.f;

    for (int kk = 0; kk < DH; kk += BK) {
        __syncthreads();
        #pragma unroll
        for (int s = 0; s < 2; s++) {
            int id  = tid + s * 256;
            int row = id >> 2, q = id & 3;
            float4 va = ((const float4*)X)[(size_t)(i0 + row) * (DH / 4) + (kk >> 2) + q];
            As[q * 4 + 0][row] = va.x;
            As[q * 4 + 1][row] = va.y;
            As[q * 4 + 2][row] = va.z;
            As[q * 4 + 3][row] = va.w;
            float4 vb = ((const float4*)X)[(size_t)(j0 + row) * (DH / 4) + (kk >> 2) + q];
            Bs[q * 4 + 0][row] = vb.x;
            Bs[q * 4 + 1][row] = vb.y;
            Bs[q * 4 + 2][row] = vb.z;
            Bs[q * 4 + 3][row] = vb.w;
        }
        __syncthreads();
        #pragma unroll
        for (int k = 0; k < BK; k++) {
            float a[8], b[8];
            *(float4*)&a[0] = *(const float4*)&As[k][ty * 8];
            *(float4*)&a[4] = *(const float4*)&As[k][ty * 8 + 4];
            *(float4*)&b[0] = *(const float4*)&Bs[k][tx * 8];
            *(float4*)&b[4] = *(const float4*)&Bs[k][tx * 8 + 4];
            #pragma unroll
            for (int ii = 0; ii < 8; ii++)
                #pragma unroll
                for (int jj = 0; jj < 8; jj++)
                    acc[ii][jj] = fmaf(a[ii], b[jj], acc[ii][jj]);
        }
    }

    // Epilogue: distances + moment accumulation.
    float sh[8], sl[8], shh[8], sll[8], shl[8];
    #pragma unroll
    for (int ii = 0; ii < 8; ii++) { sh[ii] = sl[ii] = shh[ii] = sll[ii] = shl[ii] = 0.f; }

    #pragma unroll
    for (int jj = 0; jj < 8; jj++) {
        int j = tx * 8 + jj;
        float ej[16];
        #pragma unroll
        for (int q = 0; q < 4; q++) *(float4*)&ej[q * 4] = *(const float4*)&Ej[j][q * 4];
        float sqhj = sqhJ[j], sqlj = sqlJ[j];
        #pragma unroll
        for (int ii = 0; ii < 8; ii++) {
            int i = ty * 8 + ii;
            float lg = 0.f;
            #pragma unroll
            for (int q = 0; q < 4; q++) {
                float4 vi = *(const float4*)&Ei[i][q * 4];
                lg = fmaf(vi.x, ej[q * 4 + 0], lg);
                lg = fmaf(vi.y, ej[q * 4 + 1], lg);
                lg = fmaf(vi.z, ej[q * 4 + 2], lg);
                lg = fmaf(vi.w, ej[q * 4 + 3], lg);
            }
            float h = sqrtf(fmaxf(sqhI[i] + sqhj - 2.f * acc[ii][jj], 0.f));
            float l = sqrtf(fmaxf(sqlI[i] + sqlj - 2.f * lg, 0.f));
            sh[ii] += h;
            sl[ii] += l;
            shh[ii] = fmaf(h, h, shh[ii]);
            sll[ii] = fmaf(l, l, sll[ii]);
            shl[ii] = fmaf(h, l, shl[ii]);
        }
    }

    // Reduce across the 16 tx lanes (contiguous within each half-warp), then
    // one double atomic per (row, moment).
    #pragma unroll
    for (int ii = 0; ii < 8; ii++) {
        float v0 = sh[ii], v1 = sl[ii], v2 = shh[ii], v3 = sll[ii], v4 = shl[ii];
        #pragma unroll
        for (int o = 8; o; o >>= 1) {
            v0 += __shfl_xor_sync(0xffffffffu, v0, o);
            v1 += __shfl_xor_sync(0xffffffffu, v1, o);
            v2 += __shfl_xor_sync(0xffffffffu, v2, o);
            v3 += __shfl_xor_sync(0xffffffffu, v3, o);
            v4 += __shfl_xor_sync(0xffffffffu, v4, o);
        }
        if (tx == 0) {
            int i = i0 + ty * 8 + ii;
            atomicAdd(&g_Sh[i],  (double)v0);
            atomicAdd(&g_Sl[i],  (double)v1);
            atomicAdd(&g_Shh[i], (double)v2);
            atomicAdd(&g_Sll[i], (double)v3);
            atomicAdd(&g_Shl[i], (double)v4);
        }
    }
}

// ---------------------------------------------------------------------------
// Kernel 2: UMAP cross-entropy loss (positives + NSR negatives per sample)
// ---------------------------------------------------------------------------
__global__ void __launch_bounds__(256) ce_k(const float* __restrict__ E,
                                            const int* __restrict__ perm) {
    int idx = blockIdx.x * 256 + threadIdx.x;
    float term = 0.f;
    if (idx < NTOT) {
        float s = 0.f;
        if (idx < Bn) {
            const float* p = E + (size_t)idx * 32;
            #pragma unroll
            for (int k = 0; k < DE; k++) { float d = p[k] - p[DE + k]; s = fmaf(d, d, s); }
            float d  = sqrtf(s);
            float pd = 1.f / (1.f + A_C * powf(d, PW));
            term = -logf(fmaxf(pd, EPSc));
        } else {
            int j = idx - Bn;
            const float* pt = E + (size_t)(j / NSR) * 32;            // e_to
            const float* pf = E + (size_t)(perm[j] / NSR) * 32 + DE; // e_from
            #pragma unroll
            for (int k = 0; k < DE; k++) { float d = pt[k] - pf[k]; s = fmaf(d, d, s); }
            float d  = sqrtf(s);
            float pd = 1.f / (1.f + A_C * powf(d, PW));
            term = -logf(fmaxf(1.f - pd, EPSc));   // REPULSION = 1.0
        }
    }
    #pragma unroll
    for (int o = 16; o; o >>= 1) term += __shfl_xor_sync(0xffffffffu, term, o);
    __shared__ float ws[8];
    if ((threadIdx.x & 31) == 0) ws[threadIdx.x >> 5] = term;
    __syncthreads();
    if (threadIdx.x == 0) {
        float s2 = 0.f;
        #pragma unroll
        for (int w = 0; w < 8; w++) s2 += ws[w];
        atomicAdd(&g_ce, (double)s2);
    }
}

// ---------------------------------------------------------------------------
// Kernel 3: per-row correlations -> final scalar
// ---------------------------------------------------------------------------
__global__ void __launch_bounds__(256) final_k(float* __restrict__ out) {
    int t = threadIdx.x;
    double s = 0.0;
    const double invB = 1.0 / (double)Bn;
    for (int i = t; i < Bn; i += 256) {
        double Sh = g_Sh[i], Sl = g_Sl[i];
        double num = g_Shl[i] - Sh * Sl * invB;
        double dh  = sqrt(fmax(g_Shh[i] - Sh * Sh * invB, 0.0));
        double dl  = sqrt(fmax(g_Sll[i] - Sl * Sl * invB, 0.0));
        s += num / (dh * dl);
    }
    __shared__ double red[256];
    red[t] = s;
    __syncthreads();
    for (int o = 128; o; o >>= 1) {
        if (t < o) red[t] += red[t + o];
        __syncthreads();
    }
    if (t == 0) {
        double corr   = red[0] * invB;
        double ce     = g_ce / (double)NTOT;
        out[0] = (float)(ALPHA * ce + BETA * (-corr));
    }
}

// ---------------------------------------------------------------------------
extern "C" void kernel_launch(void* const* d_in, const int* in_sizes, int n_in,
                              void* d_out, int out_size) {
    (void)in_sizes; (void)n_in; (void)out_size;
    const float* E    = (const float*)d_in[0];   // embed_to_from (4096, 32)
    const float* X    = (const float*)d_in[1];   // placeholder   (4096, 784)
    const int*   perm = (const int*)d_in[2];     // (20480,)
    float* out = (float*)d_out;

    prep_k<<<Bn, 128>>>(X, E);
    pair_k<<<dim3(Bn / BM, Bn / BNt), 256>>>(X, E);
    ce_k<<<NTOT / 256, 256>>>(E, perm);
    final_k<<<1, 256>>>(out);
}

// round 2
// speedup vs baseline: 1.8407x; 1.8407x over previous
#include <cuda_runtime.h>
#include <cuda_fp16.h>
#include <math.h>
#include <stdint.h>

// ---------------------------------------------------------------------------
// Problem constants
// ---------------------------------------------------------------------------
#define Bn    4096
#define DH    784
#define DE    16
#define NSR   5
#define NTOT  (Bn * (1 + NSR))    // 24576

__device__ __constant__ const float  A_C   = 1.576943f;
__device__ __constant__ const float  PW    = 1.7901216f;   // 2 * 0.8950608
__device__ __constant__ const float  EPSc  = 1e-4f;

// alpha/beta for BATCH_COUNT=500, TOTAL_STEPS=1000, WARMUP=50:
// beta = 0.5*(1 - 500/800)^2 = 0.0703125 ; alpha = 0.9296875
#define ALPHA 0.9296875
#define BETA  0.0703125

#define BM 128
#define BK 16
#define NTILE 32                      // 4096/128
#define ASTRIDE 268                   // floats per As row (2*BM + 12), 16B aligned
#define BSTRIDE 132

// ---------------------------------------------------------------------------
// Device scratch
// ---------------------------------------------------------------------------
__device__ double g_Sh[Bn], g_Sl[Bn], g_Shh[Bn], g_Sll[Bn], g_Shl[Bn];
__device__ float  g_sqh[Bn];
__device__ float  g_sql[Bn];
__device__ double g_ce;

// ---------------------------------------------------------------------------
// Helpers
// ---------------------------------------------------------------------------
__device__ __forceinline__ unsigned long long ffma2(unsigned long long a,
                                                    unsigned long long b,
                                                    unsigned long long c) {
    unsigned long long d;
    asm("fma.rn.f32x2 %0, %1, %2, %3;" : "=l"(d) : "l"(a), "l"(b), "l"(c));
    return d;
}
__device__ __forceinline__ float sqrt_fast(float x) {
    float y;
    asm("sqrt.approx.f32 %0, %1;" : "=f"(y) : "f"(x));
    return y;
}
__device__ __forceinline__ float lo32(unsigned long long v) {
    return __uint_as_float((unsigned)(v & 0xffffffffull));
}
__device__ __forceinline__ float hi32(unsigned long long v) {
    return __uint_as_float((unsigned)(v >> 32));
}

// ---------------------------------------------------------------------------
// Kernel 0: row norms + zero accumulators
// ---------------------------------------------------------------------------
__global__ void __launch_bounds__(128) prep_k(const float* __restrict__ X,
                                              const float* __restrict__ E) {
    int i = blockIdx.x;
    int t = threadIdx.x;
    const float* xr = X + (size_t)i * DH;
    float s = 0.f;
    for (int k = t; k < DH; k += 128) { float v = xr[k]; s = fmaf(v, v, s); }
    #pragma unroll
    for (int o = 16; o; o >>= 1) s += __shfl_xor_sync(0xffffffffu, s, o);
    __shared__ float ws[4];
    if ((t & 31) == 0) ws[t >> 5] = s;
    __syncthreads();
    if (t == 0) {
        g_sqh[i] = ws[0] + ws[1] + ws[2] + ws[3];
        const float* er = E + (size_t)i * 2 * DE;
        float sl = 0.f;
        #pragma unroll
        for (int k = 0; k < DE; k++) sl = fmaf(er[k], er[k], sl);
        g_sql[i] = sl;
        g_Sh[i] = 0.0; g_Sl[i] = 0.0; g_Shh[i] = 0.0; g_Sll[i] = 0.0; g_Shl[i] = 0.0;
        if (i == 0) g_ce = 0.0;
    }
}

// ---------------------------------------------------------------------------
// Kernel 1: symmetric fused pairwise-moment accumulation.
// Upper-triangle tiles only (528 blocks). Per tile:
//   stage 1: 16-dim low-D gram via packed-f32x2 GEMM -> l distances as half2
//   stage 2: 784-dim high-D gram via packed-f32x2 GEMM
//   epilogue: h = dist, 5 moments; rows via shfl+REDG, cols (off-diag tiles)
//             via shfl.xor16 + predicated REDG.
// ---------------------------------------------------------------------------
__global__ void __launch_bounds__(256) pair_k(const float* __restrict__ X,
                                              const float* __restrict__ E) {
    __shared__ float As[BK][ASTRIDE];    // A tile, each value DUPLICATED
    __shared__ float Bs[BK][BSTRIDE];
    __shared__ float sqhI[BM], sqhJ[BM], sqlI[BM], sqlJ[BM];

    // --- triangular tile decode: idx -> (bi, bj), bi <= bj ---
    int idx = blockIdx.x;
    int bi = 0;
    while ((bi + 1) * (65 - (bi + 1)) / 2 <= idx) bi++;
    int bj = bi + (idx - bi * (65 - bi) / 2);
    const bool offdiag = (bi != bj);

    const int i0 = bi * BM;
    const int j0 = bj * BM;
    const int tid = threadIdx.x;
    const int tx = tid & 15, ty = tid >> 4;
    const int lane = tid & 31;

    if (tid < 128) {
        sqhI[tid] = g_sqh[i0 + tid];
        sqlI[tid] = g_sql[i0 + tid];
    } else {
        int r = tid - 128;
        sqhJ[r] = g_sqh[j0 + r];
        sqlJ[r] = g_sql[j0 + r];
    }

    unsigned long long acc[8][4];
    #pragma unroll
    for (int a = 0; a < 8; a++)
        #pragma unroll
        for (int b = 0; b < 4; b++) acc[a][b] = 0ull;

    // ================= stage 1: low-D (16) gram =================
    {
        __syncthreads();
        #pragma unroll
        for (int s = 0; s < 2; s++) {
            int id  = tid + s * 256;
            int row = id >> 2, q = id & 3;
            float4 va = ((const float4*)E)[(size_t)(i0 + row) * 8 + q];
            *(float2*)&As[q * 4 + 0][2 * row] = make_float2(va.x, va.x);
            *(float2*)&As[q * 4 + 1][2 * row] = make_float2(va.y, va.y);
            *(float2*)&As[q * 4 + 2][2 * row] = make_float2(va.z, va.z);
            *(float2*)&As[q * 4 + 3][2 * row] = make_float2(va.w, va.w);
            float4 vb = ((const float4*)E)[(size_t)(j0 + row) * 8 + q];
            Bs[q * 4 + 0][row] = vb.x;
            Bs[q * 4 + 1][row] = vb.y;
            Bs[q * 4 + 2][row] = vb.z;
            Bs[q * 4 + 3][row] = vb.w;
        }
        __syncthreads();
        #pragma unroll
        for (int k = 0; k < BK; k++) {
            ulonglong2 A0 = *(const ulonglong2*)&As[k][ty * 16 + 0];
            ulonglong2 A1 = *(const ulonglong2*)&As[k][ty * 16 + 4];
            ulonglong2 A2 = *(const ulonglong2*)&As[k][ty * 16 + 8];
            ulonglong2 A3 = *(const ulonglong2*)&As[k][ty * 16 + 12];
            ulonglong2 B0 = *(const ulonglong2*)&Bs[k][tx * 8];
            unsigned long long a2[8] = {A0.x, A0.y, A1.x, A1.y, A2.x, A2.y, A3.x, A3.y};
            unsigned long long b2[4] = {B0.x, B0.y, ((const ulonglong2*)&Bs[k][tx * 8])[1].x,
                                        ((const ulonglong2*)&Bs[k][tx * 8])[1].y};
            #pragma unroll
            for (int ii = 0; ii < 8; ii++)
                #pragma unroll
                for (int jp = 0; jp < 4; jp++)
                    acc[ii][jp] = ffma2(a2[ii], b2[jp], acc[ii][jp]);
        }
    }

    // convert low-D gram -> l distances, park as half2; reset acc
    __half2 lh[8][4];
    #pragma unroll
    for (int ii = 0; ii < 8; ii++) {
        float sqli = sqlI[ty * 8 + ii];
        #pragma unroll
        for (int jp = 0; jp < 4; jp++) {
            int j = tx * 8 + jp * 2;
            float g0 = lo32(acc[ii][jp]), g1 = hi32(acc[ii][jp]);
            float l0 = sqrt_fast(fmaxf(sqli + sqlJ[j]     - 2.f * g0, 0.f));
            float l1 = sqrt_fast(fmaxf(sqli + sqlJ[j + 1] - 2.f * g1, 0.f));
            lh[ii][jp] = __floats2half2_rn(l0, l1);
            acc[ii][jp] = 0ull;
        }
    }

    // ================= stage 2: high-D (784) gram =================
    for (int kk = 0; kk < DH; kk += BK) {
        __syncthreads();
        #pragma unroll
        for (int s = 0; s < 2; s++) {
            int id  = tid + s * 256;
            int row = id >> 2, q = id & 3;
            float4 va = ((const float4*)X)[(size_t)(i0 + row) * (DH / 4) + (kk >> 2) + q];
            *(float2*)&As[q * 4 + 0][2 * row] = make_float2(va.x, va.x);
            *(float2*)&As[q * 4 + 1][2 * row] = make_float2(va.y, va.y);
            *(float2*)&As[q * 4 + 2][2 * row] = make_float2(va.z, va.z);
            *(float2*)&As[q * 4 + 3][2 * row] = make_float2(va.w, va.w);
            float4 vb = ((const float4*)X)[(size_t)(j0 + row) * (DH / 4) + (kk >> 2) + q];
            Bs[q * 4 + 0][row] = vb.x;
            Bs[q * 4 + 1][row] = vb.y;
            Bs[q * 4 + 2][row] = vb.z;
            Bs[q * 4 + 3][row] = vb.w;
        }
        __syncthreads();
        #pragma unroll
        for (int k = 0; k < BK; k++) {
            ulonglong2 A0 = *(const ulonglong2*)&As[k][ty * 16 + 0];
            ulonglong2 A1 = *(const ulonglong2*)&As[k][ty * 16 + 4];
            ulonglong2 A2 = *(const ulonglong2*)&As[k][ty * 16 + 8];
            ulonglong2 A3 = *(const ulonglong2*)&As[k][ty * 16 + 12];
            ulonglong2 B0 = ((const ulonglong2*)&Bs[k][tx * 8])[0];
            ulonglong2 B1 = ((const ulonglong2*)&Bs[k][tx * 8])[1];
            unsigned long long a2[8] = {A0.x, A0.y, A1.x, A1.y, A2.x, A2.y, A3.x, A3.y};
            unsigned long long b2[4] = {B0.x, B0.y, B1.x, B1.y};
            #pragma unroll
            for (int ii = 0; ii < 8; ii++)
                #pragma unroll
                for (int jp = 0; jp < 4; jp++)
                    acc[ii][jp] = ffma2(a2[ii], b2[jp], acc[ii][jp]);
        }
    }

    // ================= epilogue =================
    float colp[8][5];
    #pragma unroll
    for (int jj = 0; jj < 8; jj++)
        #pragma unroll
        for (int m = 0; m < 5; m++) colp[jj][m] = 0.f;

    #pragma unroll
    for (int ii = 0; ii < 8; ii++) {
        int i = ty * 8 + ii;
        float sqhi = sqhI[i];
        float r0 = 0.f, r1 = 0.f, r2 = 0.f, r3 = 0.f, r4 = 0.f;
        #pragma unroll
        for (int jp = 0; jp < 4; jp++) {
            float2 lf = __half22float2(lh[ii][jp]);
            float g0 = lo32(acc[ii][jp]), g1 = hi32(acc[ii][jp]);
            int j = tx * 8 + jp * 2;
            float h0 = sqrt_fast(fmaxf(sqhi + sqhJ[j]     - 2.f * g0, 0.f));
            float h1 = sqrt_fast(fmaxf(sqhi + sqhJ[j + 1] - 2.f * g1, 0.f));
            r0 += h0 + h1;
            r1 += lf.x + lf.y;
            r2 = fmaf(h0, h0, fmaf(h1, h1, r2));
            r3 = fmaf(lf.x, lf.x, fmaf(lf.y, lf.y, r3));
            r4 = fmaf(h0, lf.x, fmaf(h1, lf.y, r4));
            if (offdiag) {
                colp[jp * 2    ][0] += h0;
                colp[jp * 2    ][1] += lf.x;
                colp[jp * 2    ][2] = fmaf(h0, h0, colp[jp * 2][2]);
                colp[jp * 2    ][3] = fmaf(lf.x, lf.x, colp[jp * 2][3]);
                colp[jp * 2    ][4] = fmaf(h0, lf.x, colp[jp * 2][4]);
                colp[jp * 2 + 1][0] += h1;
                colp[jp * 2 + 1][1] += lf.y;
                colp[jp * 2 + 1][2] = fmaf(h1, h1, colp[jp * 2 + 1][2]);
                colp[jp * 2 + 1][3] = fmaf(lf.y, lf.y, colp[jp * 2 + 1][3]);
                colp[jp * 2 + 1][4] = fmaf(h1, lf.y, colp[jp * 2 + 1][4]);
            }
        }
        // reduce rows across the 16 tx lanes (stay inside each half-warp)
        #pragma unroll
        for (int o = 8; o; o >>= 1) {
            r0 += __shfl_xor_sync(0xffffffffu, r0, o);
            r1 += __shfl_xor_sync(0xffffffffu, r1, o);
            r2 += __shfl_xor_sync(0xffffffffu, r2, o);
            r3 += __shfl_xor_sync(0xffffffffu, r3, o);
            r4 += __shfl_xor_sync(0xffffffffu, r4, o);
        }
        if (tx == 0) {
            int gi = i0 + i;
            atomicAdd(&g_Sh[gi],  (double)r0);
            atomicAdd(&g_Sl[gi],  (double)r1);
            atomicAdd(&g_Shh[gi], (double)r2);
            atomicAdd(&g_Sll[gi], (double)r3);
            atomicAdd(&g_Shl[gi], (double)r4);
        }
    }

    // columns (transposed contribution) for off-diagonal tiles
    if (offdiag) {
        #pragma unroll
        for (int jj = 0; jj < 8; jj++) {
            #pragma unroll
            for (int m = 0; m < 5; m++)
                colp[jj][m] += __shfl_xor_sync(0xffffffffu, colp[jj][m], 16);
        }
        if (lane < 16) {
            #pragma unroll
            for (int jj = 0; jj < 8; jj++) {
                int gj = j0 + tx * 8 + jj;
                atomicAdd(&g_Sh[gj],  (double)colp[jj][0]);
                atomicAdd(&g_Sl[gj],  (double)colp[jj][1]);
                atomicAdd(&g_Shh[gj], (double)colp[jj][2]);
                atomicAdd(&g_Sll[gj], (double)colp[jj][3]);
                atomicAdd(&g_Shl[gj], (double)colp[jj][4]);
            }
        }
    }
}

// ---------------------------------------------------------------------------
// Kernel 2: UMAP cross-entropy loss
// ---------------------------------------------------------------------------
__global__ void __launch_bounds__(256) ce_k(const float* __restrict__ E,
                                            const int* __restrict__ perm) {
    int idx = blockIdx.x * 256 + threadIdx.x;
    float term = 0.f;
    if (idx < NTOT) {
        float s = 0.f;
        if (idx < Bn) {
            const float* p = E + (size_t)idx * 32;
            #pragma unroll
            for (int k = 0; k < DE; k++) { float d = p[k] - p[DE + k]; s = fmaf(d, d, s); }
            float d  = sqrtf(s);
            float pd = 1.f / (1.f + A_C * powf(d, PW));
            term = -logf(fmaxf(pd, EPSc));
        } else {
            int j = idx - Bn;
            const float* pt = E + (size_t)(j / NSR) * 32;
            const float* pf = E + (size_t)(perm[j] / NSR) * 32 + DE;
            #pragma unroll
            for (int k = 0; k < DE; k++) { float d = pt[k] - pf[k]; s = fmaf(d, d, s); }
            float d  = sqrtf(s);
            float pd = 1.f / (1.f + A_C * powf(d, PW));
            term = -logf(fmaxf(1.f - pd, EPSc));
        }
    }
    #pragma unroll
    for (int o = 16; o; o >>= 1) term += __shfl_xor_sync(0xffffffffu, term, o);
    __shared__ float ws[8];
    if ((threadIdx.x & 31) == 0) ws[threadIdx.x >> 5] = term;
    __syncthreads();
    if (threadIdx.x == 0) {
        float s2 = 0.f;
        #pragma unroll
        for (int w = 0; w < 8; w++) s2 += ws[w];
        atomicAdd(&g_ce, (double)s2);
    }
}

// ---------------------------------------------------------------------------
// Kernel 3: per-row correlations -> final scalar (float rsqrt path)
// ---------------------------------------------------------------------------
__global__ void __launch_bounds__(256) final_k(float* __restrict__ out) {
    int t = threadIdx.x;
    double s = 0.0;
    const double invB = 1.0 / (double)Bn;
    for (int i = t; i < Bn; i += 256) {
        double Sh = g_Sh[i], Sl = g_Sl[i];
        float num = (float)(g_Shl[i] - Sh * Sl * invB);
        float vh  = (float)fmax(g_Shh[i] - Sh * Sh * invB, 0.0);
        float vl  = (float)fmax(g_Sll[i] - Sl * Sl * invB, 0.0);
        s += (double)(num * rsqrtf(fmaxf(vh, 1e-30f)) * rsqrtf(fmaxf(vl, 1e-30f)));
    }
    __shared__ double red[256];
    red[t] = s;
    __syncthreads();
    for (int o = 128; o; o >>= 1) {
        if (t < o) red[t] += red[t + o];
        __syncthreads();
    }
    if (t == 0) {
        double corr = red[0] * invB;
        double ce   = g_ce / (double)NTOT;
        out[0] = (float)(ALPHA * ce + BETA * (-corr));
    }
}

// ---------------------------------------------------------------------------
extern "C" void kernel_launch(void* const* d_in, const int* in_sizes, int n_in,
                              void* d_out, int out_size) {
    (void)in_sizes; (void)n_in; (void)out_size;
    const float* E    = (const float*)d_in[0];   // embed_to_from (4096, 32)
    const float* X    = (const float*)d_in[1];   // placeholder   (4096, 784)
    const int*   perm = (const int*)d_in[2];     // (20480,)
    float* out = (float*)d_out;

    prep_k<<<Bn, 128>>>(X, E);
    pair_k<<<(NTILE * (NTILE + 1)) / 2, 256>>>(X, E);   // 528 triangular tiles
    ce_k<<<(NTOT + 255) / 256, 256>>>(E, perm);
    final_k<<<1, 256>>>(out);
}

// round 4
// speedup vs baseline: 10.0832x; 5.4778x over previous
#include <cuda_runtime.h>
#include <cuda_fp16.h>
#include <math.h>
#include <stdint.h>

// ---------------------------------------------------------------------------
// Problem constants
// ---------------------------------------------------------------------------
#define Bn    4096
#define DH    784
#define DHP   832                 // padded K (13 * 64)
#define DE    16
#define NSR   5
#define NTOT  (Bn * (1 + NSR))
#define NTILE 32
#define NBLK  (NTILE * (NTILE + 1) / 2)   // 528
#define NCH   13                  // K chunks of 64 halves

#define ALPHA 0.9296875
#define BETA  0.0703125

__device__ __constant__ const float A_C  = 1.576943f;
__device__ __constant__ const float PW   = 1.7901216f;
__device__ __constant__ const float EPSc = 1e-4f;

// smem layout (bytes)
#define SM_A    0            // [2][128][64] halves = 32768
#define SM_B    32768        // 32768
#define SM_EA   65536        // [128][16] halves = 4096
#define SM_EB   69632        // 4096
#define SM_ROW  73728        // [4][128][5] f32 = 10240
#define SM_COL  83968        // [2][128][5] f32 = 5120
#define SM_NHI  89088        // 512 each
#define SM_NHJ  89600
#define SM_NLI  90112
#define SM_NLJ  90624
#define SM_TOT  91136

// ---------------------------------------------------------------------------
// Device scratch
// ---------------------------------------------------------------------------
__device__ __half  g_Xh[(size_t)Bn * DHP];  // fp16 X, zero-padded
__device__ __half  g_Eh[(size_t)Bn * DE];   // fp16 e_to
__device__ double  g_Sh[Bn], g_Sl[Bn], g_Shh[Bn], g_Sll[Bn], g_Shl[Bn];
__device__ float   g_sqh[Bn];
__device__ float   g_sql[Bn];
__device__ double  g_ce;
__device__ double  g_corr;

// ---------------------------------------------------------------------------
// Helpers
// ---------------------------------------------------------------------------
__device__ __forceinline__ uint32_t s2u(const void* p) {
    uint32_t a;
    asm("{ .reg .u64 t; cvta.to.shared.u64 t, %1; cvt.u32.u64 %0, t; }"
        : "=r"(a) : "l"(p));
    return a;
}
__device__ __forceinline__ float sqrt_fast(float x) {
    float y; asm("sqrt.approx.f32 %0, %1;" : "=f"(y) : "f"(x)); return y;
}
__device__ __forceinline__ void cpa16(uint32_t dst, const void* src) {
    asm volatile("cp.async.cg.shared.global [%0], [%1], 16;"
                 :: "r"(dst), "l"(src) : "memory");
}
__device__ __forceinline__ void ldsm4(uint32_t* r, uint32_t addr) {
    asm volatile("ldmatrix.sync.aligned.m8n8.x4.shared.b16 {%0,%1,%2,%3}, [%4];"
                 : "=r"(r[0]), "=r"(r[1]), "=r"(r[2]), "=r"(r[3]) : "r"(addr));
}
__device__ __forceinline__ void mma16816(float* d, const uint32_t* a, const uint32_t* b) {
    asm volatile(
        "mma.sync.aligned.m16n8k16.row.col.f32.f16.f16.f32 "
        "{%0,%1,%2,%3}, {%4,%5,%6,%7}, {%8,%9}, {%0,%1,%2,%3};"
        : "+f"(d[0]), "+f"(d[1]), "+f"(d[2]), "+f"(d[3])
        : "r"(a[0]), "r"(a[1]), "r"(a[2]), "r"(a[3]), "r"(b[0]), "r"(b[1]));
}

// ---------------------------------------------------------------------------
// Kernel 0: fp16 conversion + norms (from rounded values) + zero accumulators
// ---------------------------------------------------------------------------
__global__ void __launch_bounds__(256) prep_k(const float* __restrict__ X,
                                              const float* __restrict__ E) {
    int row = blockIdx.x;
    int t = threadIdx.x;
    const float* xr = X + (size_t)row * DH;
    __half* dst = g_Xh + (size_t)row * DHP;
    float s = 0.f;
    for (int k = t; k < DHP; k += 256) {
        float v = (k < DH) ? xr[k] : 0.f;
        __half h = __float2half(v);
        dst[k] = h;
        float vf = __half2float(h);
        s = fmaf(vf, vf, s);
    }
    #pragma unroll
    for (int o = 16; o; o >>= 1) s += __shfl_xor_sync(0xffffffffu, s, o);
    __shared__ float ws[8];
    if ((t & 31) == 0) ws[t >> 5] = s;
    __syncthreads();
    if (t < 16) {
        g_Eh[(size_t)row * DE + t] = __float2half(E[(size_t)row * 32 + t]);
    }
    if (t == 0) {
        float tot = 0.f;
        #pragma unroll
        for (int w = 0; w < 8; w++) tot += ws[w];
        g_sqh[row] = tot;
        float sl = 0.f;
        #pragma unroll
        for (int k = 0; k < DE; k++) {
            float v = __half2float(__float2half(E[(size_t)row * 32 + k]));
            sl = fmaf(v, v, sl);
        }
        g_sql[row] = sl;
        g_Sh[row] = 0.0; g_Sl[row] = 0.0; g_Shh[row] = 0.0;
        g_Sll[row] = 0.0; g_Shl[row] = 0.0;
        if (row == 0) { g_ce = 0.0; g_corr = 0.0; }
    }
}

// ---------------------------------------------------------------------------
// Kernel 1: HMMA pairwise-moment tiles (triangular, 528 blocks, 256 threads)
// ---------------------------------------------------------------------------
__global__ void __launch_bounds__(256, 1) pair_k() {
    extern __shared__ __align__(16) char smem[];
    const uint32_t sb = s2u(smem);
    const int tid = threadIdx.x;
    const int lane = tid & 31, wid = tid >> 5;
    const int wr = wid >> 2, wc = wid & 3;

    // triangular tile decode
    int idx = blockIdx.x, bi = 0;
    while ((bi + 1) * (65 - (bi + 1)) / 2 <= idx) bi++;
    int bj = bi + (idx - bi * (65 - bi) / 2);
    const bool offdiag = (bi != bj);
    const int i0 = bi * 128, j0 = bj * 128;

    float* nhI = (float*)(smem + SM_NHI);
    float* nhJ = (float*)(smem + SM_NHJ);
    float* nlI = (float*)(smem + SM_NLI);
    float* nlJ = (float*)(smem + SM_NLJ);
    if (tid < 128) {
        nhI[tid] = g_sqh[i0 + tid];
        nlI[tid] = g_sql[i0 + tid];
    } else {
        int r = tid - 128;
        nhJ[r] = g_sqh[j0 + r];
        nlJ[r] = g_sql[j0 + r];
    }

    const __half* XA = g_Xh + (size_t)i0 * DHP;
    const __half* XB = g_Xh + (size_t)j0 * DHP;

    // E tiles (1 cp.async per thread per side)
    {
        int row = tid >> 1, u = tid & 1;
        cpa16(sb + SM_EA + row * 32 + u * 16, g_Eh + (size_t)(i0 + row) * DE + u * 8);
        cpa16(sb + SM_EB + row * 32 + u * 16, g_Eh + (size_t)(j0 + row) * DE + u * 8);
    }
    // chunk 0
    #pragma unroll
    for (int p = 0; p < 4; p++) {
        int id = tid + p * 256;
        int row = id >> 3, u = id & 7;
        uint32_t sw = (uint32_t)((u ^ (row & 7)) << 4);
        cpa16(sb + SM_A + row * 128 + sw, XA + (size_t)row * DHP + u * 8);
        cpa16(sb + SM_B + row * 128 + sw, XB + (size_t)row * DHP + u * 8);
    }
    asm volatile("cp.async.commit_group;" ::: "memory");
    asm volatile("cp.async.wait_group 0;" ::: "memory");
    __syncthreads();

    // per-thread fragment address components
    const int rbaseA = wr * 64 + (lane & 15);
    const int duA    = lane >> 4;
    const int rmA    = rbaseA & 7;
    const int nbase  = wc * 32 + (lane & 7) + ((lane >> 4) << 3);
    const int duB    = (lane >> 3) & 1;
    const int rmB    = lane & 7;

    float acc[4][4][4];
    #pragma unroll
    for (int a = 0; a < 4; a++)
        #pragma unroll
        for (int b = 0; b < 4; b++)
            #pragma unroll
            for (int c = 0; c < 4; c++) acc[a][b][c] = 0.f;

    // ---------------- low-D (16) gram: single k-step ----------------
    {
        uint32_t ea[4][4], eb[2][4];
        #pragma unroll
        for (int mi = 0; mi < 4; mi++) {
            int rE = rbaseA + mi * 16;
            ldsm4(ea[mi], sb + SM_EA + rE * 32 + (duA << 4));
        }
        #pragma unroll
        for (int nt = 0; nt < 2; nt++) {
            int nE = nbase + nt * 16;
            ldsm4(eb[nt], sb + SM_EB + nE * 32 + (duB << 4));
        }
        #pragma unroll
        for (int mi = 0; mi < 4; mi++)
            #pragma unroll
            for (int ni = 0; ni < 4; ni++)
                mma16816(acc[mi][ni], ea[mi], &eb[ni >> 1][(ni & 1) * 2]);
    }
    // convert to l distances (half2), reset acc
    __half2 lhp[4][4][2];
    #pragma unroll
    for (int mi = 0; mi < 4; mi++) {
        int r0 = wr * 64 + mi * 16 + (lane >> 2), r1 = r0 + 8;
        float nl0 = nlI[r0], nl1 = nlI[r1];
        #pragma unroll
        for (int ni = 0; ni < 4; ni++) {
            int c0 = wc * 32 + ni * 8 + ((lane & 3) << 1), c1 = c0 + 1;
            float ol0 = nlJ[c0], ol1 = nlJ[c1];
            float l00 = sqrt_fast(fmaxf(fmaf(-2.f, acc[mi][ni][0], nl0 + ol0), 0.f));
            float l01 = sqrt_fast(fmaxf(fmaf(-2.f, acc[mi][ni][1], nl0 + ol1), 0.f));
            float l10 = sqrt_fast(fmaxf(fmaf(-2.f, acc[mi][ni][2], nl1 + ol0), 0.f));
            float l11 = sqrt_fast(fmaxf(fmaf(-2.f, acc[mi][ni][3], nl1 + ol1), 0.f));
            lhp[mi][ni][0] = __floats2half2_rn(l00, l01);
            lhp[mi][ni][1] = __floats2half2_rn(l10, l11);
            acc[mi][ni][0] = 0.f; acc[mi][ni][1] = 0.f;
            acc[mi][ni][2] = 0.f; acc[mi][ni][3] = 0.f;
        }
    }

    // ---------------- high-D mainloop: 13 chunks x 4 k-steps ----------------
    for (int c = 0; c < NCH; c++) {
        if (c + 1 < NCH) {
            uint32_t dA = sb + SM_A + (((c + 1) & 1) << 14);
            uint32_t dB = sb + SM_B + (((c + 1) & 1) << 14);
            const __half* pA = XA + (c + 1) * 64;
            const __half* pB = XB + (c + 1) * 64;
            #pragma unroll
            for (int p = 0; p < 4; p++) {
                int id = tid + p * 256;
                int row = id >> 3, u = id & 7;
                uint32_t sw = (uint32_t)((u ^ (row & 7)) << 4);
                cpa16(dA + row * 128 + sw, pA + (size_t)row * DHP + u * 8);
                cpa16(dB + row * 128 + sw, pB + (size_t)row * DHP + u * 8);
            }
            asm volatile("cp.async.commit_group;" ::: "memory");
            asm volatile("cp.async.wait_group 1;" ::: "memory");
        } else {
            asm volatile("cp.async.wait_group 0;" ::: "memory");
        }
        __syncthreads();

        uint32_t bA = sb + SM_A + ((c & 1) << 14);
        uint32_t bB = sb + SM_B + ((c & 1) << 14);
        #pragma unroll
        for (int ks = 0; ks < 4; ks++) {
            uint32_t afr[4][4], bfr[2][4];
            #pragma unroll
            for (int mi = 0; mi < 4; mi++) {
                int row = rbaseA + mi * 16;
                ldsm4(afr[mi], bA + row * 128 + (((2 * ks + duA) ^ rmA) << 4));
            }
            #pragma unroll
            for (int nt = 0; nt < 2; nt++) {
                int nb = nbase + nt * 16;
                ldsm4(bfr[nt], bB + nb * 128 + (((2 * ks + duB) ^ rmB) << 4));
            }
            #pragma unroll
            for (int mi = 0; mi < 4; mi++)
                #pragma unroll
                for (int ni = 0; ni < 4; ni++)
                    mma16816(acc[mi][ni], afr[mi], &bfr[ni >> 1][(ni & 1) * 2]);
        }
        __syncthreads();
    }

    // ---------------- epilogue: distances + moments ----------------
    float* rowSm = (float*)(smem + SM_ROW);
    float* colSm = (float*)(smem + SM_COL);
    float cacc[4][2][5];
    #pragma unroll
    for (int ni = 0; ni < 4; ni++)
        #pragma unroll
        for (int q = 0; q < 2; q++)
            #pragma unroll
            for (int m = 0; m < 5; m++) cacc[ni][q][m] = 0.f;

    #pragma unroll
    for (int mi = 0; mi < 4; mi++) {
        int r0 = wr * 64 + mi * 16 + (lane >> 2), r1 = r0 + 8;
        float nh0 = nhI[r0], nh1 = nhI[r1];
        float rA[5] = {0.f, 0.f, 0.f, 0.f, 0.f};
        float rB[5] = {0.f, 0.f, 0.f, 0.f, 0.f};
        #pragma unroll
        for (int ni = 0; ni < 4; ni++) {
            int c0 = wc * 32 + ni * 8 + ((lane & 3) << 1), c1 = c0 + 1;
            float oh0 = nhJ[c0], oh1 = nhJ[c1];
            float h00 = sqrt_fast(fmaxf(fmaf(-2.f, acc[mi][ni][0], nh0 + oh0), 0.f));
            float h01 = sqrt_fast(fmaxf(fmaf(-2.f, acc[mi][ni][1], nh0 + oh1), 0.f));
            float h10 = sqrt_fast(fmaxf(fmaf(-2.f, acc[mi][ni][2], nh1 + oh0), 0.f));
            float h11 = sqrt_fast(fmaxf(fmaf(-2.f, acc[mi][ni][3], nh1 + oh1), 0.f));
            float2 lp0 = __half22float2(lhp[mi][ni][0]);
            float2 lp1 = __half22float2(lhp[mi][ni][1]);
            // row r0
            rA[0] += h00 + h01;
            rA[1] += lp0.x + lp0.y;
            rA[2] = fmaf(h00, h00, fmaf(h01, h01, rA[2]));
            rA[3] = fmaf(lp0.x, lp0.x, fmaf(lp0.y, lp0.y, rA[3]));
            rA[4] = fmaf(h00, lp0.x, fmaf(h01, lp0.y, rA[4]));
            // row r1
            rB[0] += h10 + h11;
            rB[1] += lp1.x + lp1.y;
            rB[2] = fmaf(h10, h10, fmaf(h11, h11, rB[2]));
            rB[3] = fmaf(lp1.x, lp1.x, fmaf(lp1.y, lp1.y, rB[3]));
            rB[4] = fmaf(h10, lp1.x, fmaf(h11, lp1.y, rB[4]));
            // col c0
            cacc[ni][0][0] += h00 + h10;
            cacc[ni][0][1] += lp0.x + lp1.x;
            cacc[ni][0][2] = fmaf(h00, h00, fmaf(h10, h10, cacc[ni][0][2]));
            cacc[ni][0][3] = fmaf(lp0.x, lp0.x, fmaf(lp1.x, lp1.x, cacc[ni][0][3]));
            cacc[ni][0][4] = fmaf(h00, lp0.x, fmaf(h10, lp1.x, cacc[ni][0][4]));
            // col c1
            cacc[ni][1][0] += h01 + h11;
            cacc[ni][1][1] += lp0.y + lp1.y;
            cacc[ni][1][2] = fmaf(h01, h01, fmaf(h11, h11, cacc[ni][1][2]));
            cacc[ni][1][3] = fmaf(lp0.y, lp0.y, fmaf(lp1.y, lp1.y, cacc[ni][1][3]));
            cacc[ni][1][4] = fmaf(h01, lp0.y, fmaf(h11, lp1.y, cacc[ni][1][4]));
        }
        // reduce rows over the 4 lanes sharing the same row (lane%4 group)
        #pragma unroll
        for (int m = 0; m < 5; m++) {
            rA[m] += __shfl_xor_sync(0xffffffffu, rA[m], 1);
            rA[m] += __shfl_xor_sync(0xffffffffu, rA[m], 2);
            rB[m] += __shfl_xor_sync(0xffffffffu, rB[m], 1);
            rB[m] += __shfl_xor_sync(0xffffffffu, rB[m], 2);
        }
        if ((lane & 3) == 0) {
            #pragma unroll
            for (int m = 0; m < 5; m++) {
                rowSm[(wc * 128 + r0) * 5 + m] = rA[m];
                rowSm[(wc * 128 + r1) * 5 + m] = rB[m];
            }
        }
    }
    // reduce cols over the 8 lanes sharing the same cols (lane>>2 groups)
    #pragma unroll
    for (int ni = 0; ni < 4; ni++)
        #pragma unroll
        for (int q = 0; q < 2; q++)
            #pragma unroll
            for (int m = 0; m < 5; m++) {
                float v = cacc[ni][q][m];
                v += __shfl_xor_sync(0xffffffffu, v, 4);
                v += __shfl_xor_sync(0xffffffffu, v, 8);
                v += __shfl_xor_sync(0xffffffffu, v, 16);
                cacc[ni][q][m] = v;
            }
    if (lane < 4) {
        #pragma unroll
        for (int ni = 0; ni < 4; ni++) {
            int c0 = wc * 32 + ni * 8 + (lane << 1);
            #pragma unroll
            for (int m = 0; m < 5; m++) {
                colSm[(wr * 128 + c0) * 5 + m]     = cacc[ni][0][m];
                colSm[(wr * 128 + c0 + 1) * 5 + m] = cacc[ni][1][m];
            }
        }
    }
    __syncthreads();

    // final per-(row|col) REDG
    if (tid < 128) {
        int r = tid;
        float s0 = 0.f, s1 = 0.f, s2 = 0.f, s3 = 0.f, s4 = 0.f;
        #pragma unroll
        for (int w = 0; w < 4; w++) {
            const float* p = &rowSm[(w * 128 + r) * 5];
            s0 += p[0]; s1 += p[1]; s2 += p[2]; s3 += p[3]; s4 += p[4];
        }
        int gi = i0 + r;
        atomicAdd(&g_Sh[gi],  (double)s0);
        atomicAdd(&g_Sl[gi],  (double)s1);
        atomicAdd(&g_Shh[gi], (double)s2);
        atomicAdd(&g_Sll[gi], (double)s3);
        atomicAdd(&g_Shl[gi], (double)s4);
    } else if (offdiag) {
        int cjj = tid - 128;
        float s0 = 0.f, s1 = 0.f, s2 = 0.f, s3 = 0.f, s4 = 0.f;
        #pragma unroll
        for (int w = 0; w < 2; w++) {
            const float* p = &colSm[(w * 128 + cjj) * 5];
            s0 += p[0]; s1 += p[1]; s2 += p[2]; s3 += p[3]; s4 += p[4];
        }
        int gj = j0 + cjj;
        atomicAdd(&g_Sh[gj],  (double)s0);
        atomicAdd(&g_Sl[gj],  (double)s1);
        atomicAdd(&g_Shh[gj], (double)s2);
        atomicAdd(&g_Sll[gj], (double)s3);
        atomicAdd(&g_Shl[gj], (double)s4);
    }
}

// ---------------------------------------------------------------------------
// Kernel 2: UMAP cross-entropy loss (full f32 precision)
// ---------------------------------------------------------------------------
__global__ void __launch_bounds__(256) ce_k(const float* __restrict__ E,
                                            const int* __restrict__ perm) {
    int idx = blockIdx.x * 256 + threadIdx.x;
    float term = 0.f;
    if (idx < NTOT) {
        float s = 0.f;
        if (idx < Bn) {
            const float* p = E + (size_t)idx * 32;
            #pragma unroll
            for (int k = 0; k < DE; k++) { float d = p[k] - p[DE + k]; s = fmaf(d, d, s); }
            float d  = sqrtf(s);
            float pd = 1.f / (1.f + A_C * powf(d, PW));
            term = -logf(fmaxf(pd, EPSc));
        } else {
            int j = idx - Bn;
            const float* pt = E + (size_t)(j / NSR) * 32;
            const float* pf = E + (size_t)(perm[j] / NSR) * 32 + DE;
            #pragma unroll
            for (int k = 0; k < DE; k++) { float d = pt[k] - pf[k]; s = fmaf(d, d, s); }
            float d  = sqrtf(s);
            float pd = 1.f / (1.f + A_C * powf(d, PW));
            term = -logf(fmaxf(1.f - pd, EPSc));
        }
    }
    #pragma unroll
    for (int o = 16; o; o >>= 1) term += __shfl_xor_sync(0xffffffffu, term, o);
    __shared__ float ws[8];
    if ((threadIdx.x & 31) == 0) ws[threadIdx.x >> 5] = term;
    __syncthreads();
    if (threadIdx.x == 0) {
        float s2 = 0.f;
        #pragma unroll
        for (int w = 0; w < 8; w++) s2 += ws[w];
        atomicAdd(&g_ce, (double)s2);
    }
}

// ---------------------------------------------------------------------------
// Kernel 3: per-row correlations
// ---------------------------------------------------------------------------
__global__ void __launch_bounds__(256) corr_k() {
    int i = blockIdx.x * 256 + threadIdx.x;
    const double invB = 1.0 / (double)Bn;
    double Sh = g_Sh[i], Sl = g_Sl[i];
    float num = (float)(g_Shl[i] - Sh * Sl * invB);
    float vh  = (float)fmax(g_Shh[i] - Sh * Sh * invB, 0.0);
    float vl  = (float)fmax(g_Sll[i] - Sl * Sl * invB, 0.0);
    float c = num * rsqrtf(fmaxf(vh, 1e-30f)) * rsqrtf(fmaxf(vl, 1e-30f));
    atomicAdd(&g_corr, (double)c);
}

// ---------------------------------------------------------------------------
// Kernel 4: finish
// ---------------------------------------------------------------------------
__global__ void finish_k(float* __restrict__ out) {
    double corr = g_corr / (double)Bn;
    double ce   = g_ce / (double)NTOT;
    out[0] = (float)(ALPHA * ce - BETA * corr);
}

// ---------------------------------------------------------------------------
extern "C" void kernel_launch(void* const* d_in, const int* in_sizes, int n_in,
                              void* d_out, int out_size) {
    (void)in_sizes; (void)n_in; (void)out_size;
    const float* E    = (const float*)d_in[0];
    const float* X    = (const float*)d_in[1];
    const int*   perm = (const int*)d_in[2];
    float* out = (float*)d_out;

    cudaFuncSetAttribute(pair_k, cudaFuncAttributeMaxDynamicSharedMemorySize, SM_TOT);

    prep_k<<<Bn, 256>>>(X, E);
    pair_k<<<NBLK, 256, SM_TOT>>>();
    ce_k<<<(NTOT + 255) / 256, 256>>>(E, perm);
    corr_k<<<Bn / 256, 256>>>();
    finish_k<<<1, 1>>>(out);
}